// round 8
// baseline (speedup 1.0000x reference)
#include <cuda_runtime.h>
#include <math.h>

// CapsuleLayer dynamic routing, fully fused, weight-slab resident in SMEM.
//   x: (4,256,14,14) f32   weight: (32,288,8,16) f32   out: (4,512,12,12) f32
// Grid (9,32): CTA = (16 position-groups, output capsule o). 576 threads =
// two 288-thread halves, decoupled by NAMED per-half barriers; each half does
// one 4-position group per outer iteration. Weights staged once per CTA
// (coalesced LDG, swizzled conflict-free STS/LDS). Routing: softmax without
// max-shift, Z fused into a single 17-component block reduction.

#define GPOS 4
#define HALF_THR 288
#define NTHR 576
#define NWARP 9
#define GROUPS_PER_CHUNK 16
#define ITERS_PER_CTA 8

__device__ __forceinline__ void barh(int id) {
    asm volatile("bar.sync %0, %1;" :: "r"(id), "r"(HALF_THR) : "memory");
}

__global__ __launch_bounds__(NTHR, 1)
void caps_route_kernel(const float* __restrict__ x,
                       const float* __restrict__ w,
                       float* __restrict__ out)
{
    extern __shared__ float smem[];
    float4* s_w4   = (float4*)smem;                  // 288*32 float4 = 147456 B
    float*  s_x    = smem + 288 * 32 * 4;            // 2 * 4608
    float*  s_part = s_x + 2 * 4608;                 // 2 * 9 * 17
    float*  s_red  = s_part + 2 * NWARP * 17;        // 2 * 17
    float*  s_out  = s_red + 2 * 17;                 // 2 * 64

    const int tid  = threadIdx.x;
    const int h    = (tid >= HALF_THR) ? 1 : 0;
    const int htid = tid - h * HALF_THR;             // 0..287 == route k
    const int lane = tid & 31;
    const int wh   = htid >> 5;                      // warp-in-half == kk
    const int bid  = 1 + h;                          // named barrier id

    float* s_xh    = s_x    + h * 4608;
    float* s_parth = s_part + h * NWARP * 17;
    float* s_redh  = s_red  + h * 17;
    float* s_outh  = s_out  + h * 64;

    const int o = blockIdx.y;

    // ---- stage full weight slab for o (147 KB), once per CTA
    {
        const float4* wbase = (const float4*)(w + (size_t)o * 288 * 128);
#pragma unroll
        for (int pass = 0; pass < 16; ++pass) {
            int idx = tid + pass * NTHR;             // warp reads one k, j=lane
            int k = idx >> 5;
            int j = idx & 31;
            s_w4[k * 32 + (j & ~7) + ((j & 7) ^ (k & 7))] = wbase[idx];
        }
    }
    __syncthreads();    // only cross-half sync in the kernel

    // ---- strength-reduced x-staging constants (288 = 16*18 -> c = c0+16*pass)
    const int c0  = htid / 18;                       // 0..15
    const int rr  = htid - c0 * 18;                  // 0..17
    const int khh = rr / 6;
    const int ww  = rr - khh * 6;
    const int kh  = wh / 3;
    const int kw  = wh - 3 * kh;
    const float* sxbase = s_xh + (kh * 6 + kw) * 256 + lane;   // lane == inc
    float* sxw = s_xh + (khh * 6 + ww) * 256 + (c0 & 7) * 32 + (c0 >> 3);

#pragma unroll 1
    for (int itg = 0; itg < ITERS_PER_CTA; ++itg) {
        const int nb  = blockIdx.x * GROUPS_PER_CHUNK + itg * 2 + h;
        const int b   = nb / 36;
        const int r   = nb - b * 36;
        const int oh  = r / 3;
        const int ow0 = (r - oh * 3) * GPOS;

        // ---- stage x patch (per half); c&7 and rr are pass-invariant
        {
            const float* xsrc = x + ((size_t)b * 256 + c0) * 196
                                  + (oh + khh) * 14 + ow0 + ww;
#pragma unroll
            for (int pass = 0; pass < 16; ++pass)
                sxw[pass * 2] = xsrc[pass * 3136];   // c>>3 advances by 2
        }
        barh(bid);

        // ---- priors: pr[g][c] = sum_i x[g][k][i] * w[o][k][i][c]
        float pr[GPOS][16];
#pragma unroll
        for (int g = 0; g < GPOS; ++g)
#pragma unroll
            for (int c = 0; c < 16; ++c) pr[g][c] = 0.0f;

#pragma unroll
        for (int i = 0; i < 8; ++i) {
            float wv[16];
#pragma unroll
            for (int jj = 0; jj < 4; ++jj) {
                int j = i * 4 + jj;
                float4 q = s_w4[htid * 32 + (j & ~7) + ((j & 7) ^ (htid & 7))];
                wv[jj * 4 + 0] = q.x; wv[jj * 4 + 1] = q.y;
                wv[jj * 4 + 2] = q.z; wv[jj * 4 + 3] = q.w;
            }
#pragma unroll
            for (int g = 0; g < GPOS; ++g) {
                float t = sxbase[i * 32 + g * 256];
#pragma unroll
                for (int c = 0; c < 16; ++c) pr[g][c] = fmaf(t, wv[c], pr[g][c]);
            }
        }

        // ---- dynamic routing (per half, per position g)
#pragma unroll 1
        for (int g = 0; g < GPOS; ++g) {
            float logit = 0.0f;
            float outv  = 0.0f;

#pragma unroll
            for (int it = 0; it < 3; ++it) {
                // unnormalized weight e (softmax shift-free; logits bounded)
                float e = (it == 0) ? 1.0f : __expf(logit);

                float y[16];
#pragma unroll
                for (int c = 0; c < 16; ++c) y[c] = e * pr[g][c];
                float z = e;
#pragma unroll
                for (int off = 16; off; off >>= 1)
                    z += __shfl_xor_sync(0xffffffffu, z, off);

                // reduce-scatter butterfly: 16 comps -> lane pairs
#pragma unroll
                for (int c = 0; c < 8; ++c) {
                    float snd = (lane & 16) ? y[c] : y[c + 8];
                    float rcv = __shfl_xor_sync(0xffffffffu, snd, 16);
                    y[c] = ((lane & 16) ? y[c + 8] : y[c]) + rcv;
                }
#pragma unroll
                for (int c = 0; c < 4; ++c) {
                    float snd = (lane & 8) ? y[c] : y[c + 4];
                    float rcv = __shfl_xor_sync(0xffffffffu, snd, 8);
                    y[c] = ((lane & 8) ? y[c + 4] : y[c]) + rcv;
                }
#pragma unroll
                for (int c = 0; c < 2; ++c) {
                    float snd = (lane & 4) ? y[c] : y[c + 2];
                    float rcv = __shfl_xor_sync(0xffffffffu, snd, 4);
                    y[c] = ((lane & 4) ? y[c + 2] : y[c]) + rcv;
                }
                {
                    float snd = (lane & 2) ? y[0] : y[1];
                    float rcv = __shfl_xor_sync(0xffffffffu, snd, 2);
                    y[0] = ((lane & 2) ? y[1] : y[0]) + rcv;
                }
                y[0] += __shfl_xor_sync(0xffffffffu, y[0], 1);
                // lane l holds warp-sum of component (l>>1)&15; all lanes have z

                barh(bid);                               // prev readers done
                if (!(lane & 1)) s_parth[wh * 17 + ((lane >> 1) & 15)] = y[0];
                if (lane == 1)   s_parth[wh * 17 + 16] = z;
                barh(bid);
                if (htid < 17) {
                    float a = 0.0f;
#pragma unroll
                    for (int wq = 0; wq < NWARP; ++wq) a += s_parth[wq * 17 + htid];
                    s_redh[htid] = a;
                }
                barh(bid);

                // normalize + squash + logit update, all in registers
                float Z    = s_redh[16];
                float invZ = __fdividef(1.0f, Z);
                float sq = 0.0f, d = 0.0f;
#pragma unroll
                for (int c = 0; c < 16; ++c) {
                    float v = s_redh[c];                 // unnormalized s-hat
                    sq = fmaf(v, v, sq);
                    d  = fmaf(pr[g][c], v, d);
                }
                sq *= invZ * invZ;
                float scale = __fdividef(sqrtf(sq), 1.0f + sq);
                if (it < 2) logit += scale * (d * invZ);
                else        outv  = scale * invZ;
            }

            if (htid < 16) s_outh[htid * GPOS + g] = s_redh[htid] * outv;
        }

        barh(bid);
        // ---- output: 64 threads/half, 16 rows x 4 contiguous floats
        if (htid < 16 * GPOS) {
            int c = htid >> 2;
            int g = htid & 3;
            out[(((size_t)b * 512 + o * 16 + c) * 12 + oh) * 12 + (ow0 + g)]
                = s_outh[c * GPOS + g];
        }
    }
}

extern "C" void kernel_launch(void* const* d_in, const int* in_sizes, int n_in,
                              void* d_out, int out_size)
{
    const float* x = (const float*)d_in[0];
    const float* w = (const float*)d_in[1];
    if (n_in >= 2 && in_sizes[0] == 32 * 288 * 8 * 16 && in_sizes[1] == 4 * 256 * 14 * 14) {
        x = (const float*)d_in[1];
        w = (const float*)d_in[0];
    }
    const int smem_bytes = (288 * 32 * 4 + 2 * 4608 + 2 * NWARP * 17 + 2 * 17
                            + 2 * 64) * (int)sizeof(float);
    cudaFuncSetAttribute(caps_route_kernel,
                         cudaFuncAttributeMaxDynamicSharedMemorySize, smem_bytes);
    dim3 grid(9, 32);   // (position chunk) x (out capsule)
    caps_route_kernel<<<grid, NTHR, smem_bytes>>>(x, w, (float*)d_out);
}

// round 9
// speedup vs baseline: 1.6025x; 1.6025x over previous
#include <cuda_runtime.h>
#include <math.h>

// CapsuleLayer dynamic routing, fully fused, weight-slab resident in SMEM.
//   x: (4,256,14,14) f32   weight: (32,288,8,16) f32   out: (4,512,12,12) f32
// Grid (9,32): CTA = (16 position-groups, output capsule o). 576 threads =
// two 288-thread halves; each half owns one 4-position group per outer iter.
// Weights staged once per CTA (coalesced LDG, swizzled conflict-free STS/LDS).
// Routing: shift-free softmax with Z fused into one 17-component block
// reduction; s_part/s_red double-buffered -> 2 __syncthreads per iteration.

#define GPOS 4
#define HALF_THR 288
#define NTHR 576
#define NWARP 9
#define GROUPS_PER_CHUNK 16
#define ITERS_PER_CTA 8

__global__ __launch_bounds__(NTHR, 1)
void caps_route_kernel(const float* __restrict__ x,
                       const float* __restrict__ w,
                       float* __restrict__ out)
{
    extern __shared__ float smem[];
    float4* s_w4   = (float4*)smem;                  // 288*32 float4 = 147456 B
    float*  s_x    = smem + 288 * 32 * 4;            // 2 halves * 4608
    float*  s_part = s_x + 2 * 4608;                 // 2 buf * 2 halves * 9*17
    float*  s_red  = s_part + 2 * 2 * NWARP * 17;    // 2 buf * 2 halves * 17
    float*  s_out  = s_red + 2 * 2 * 17;             // 2 halves * 64

    const int tid  = threadIdx.x;
    const int h    = (tid >= HALF_THR) ? 1 : 0;
    const int htid = tid - h * HALF_THR;             // 0..287 == route k
    const int lane = tid & 31;
    const int wh   = htid >> 5;                      // warp-in-half == kk

    float* s_xh   = s_x   + h * 4608;
    float* s_outh = s_out + h * 64;
    // buffer-indexed views: s_parth[buf] base, s_redh[buf] base
    float* s_part_h = s_part + h * NWARP * 17;       // + buf*2*NWARP*17
    float* s_red_h  = s_red  + h * 17;               // + buf*2*17

    const int o = blockIdx.y;

    // ---- stage full weight slab for o (147 KB), once per CTA
    {
        const float4* wbase = (const float4*)(w + (size_t)o * 288 * 128);
#pragma unroll
        for (int pass = 0; pass < 16; ++pass) {
            int idx = tid + pass * NTHR;             // warp reads one k, j=lane
            int k = idx >> 5;
            int j = idx & 31;
            s_w4[k * 32 + (j & ~7) + ((j & 7) ^ (k & 7))] = wbase[idx];
        }
    }

    // ---- strength-reduced x-staging constants (288 = 16*18)
    const int c0  = htid / 18;                       // 0..15
    const int rr  = htid - c0 * 18;                  // 0..17
    const int khh = rr / 6;
    const int ww  = rr - khh * 6;
    const int kh  = wh / 3;
    const int kw  = wh - 3 * kh;
    const float* sxbase = s_xh + (kh * 6 + kw) * 256 + lane;   // lane == inc
    float* sxw = s_xh + (khh * 6 + ww) * 256 + (c0 & 7) * 32 + (c0 >> 3);

    int pb = 0;                                      // reduction buffer parity

#pragma unroll 1
    for (int itg = 0; itg < ITERS_PER_CTA; ++itg) {
        const int nb  = blockIdx.x * GROUPS_PER_CHUNK + itg * 2 + h;
        const int b   = nb / 36;
        const int r   = nb - b * 36;
        const int oh  = r / 3;
        const int ow0 = (r - oh * 3) * GPOS;

        // ---- stage x patch (per half); indices pass-invariant
        {
            const float* xsrc = x + ((size_t)b * 256 + c0) * 196
                                  + (oh + khh) * 14 + ow0 + ww;
#pragma unroll
            for (int pass = 0; pass < 16; ++pass)
                sxw[pass * 2] = xsrc[pass * 3136];
        }
        __syncthreads();                             // x ready (+ weights, itg=0)

        // ---- priors: pr[g][c] = sum_i x[g][k][i] * w[o][k][i][c]
        float pr[GPOS][16];
#pragma unroll
        for (int g = 0; g < GPOS; ++g)
#pragma unroll
            for (int c = 0; c < 16; ++c) pr[g][c] = 0.0f;

#pragma unroll
        for (int i = 0; i < 8; ++i) {
            float wv[16];
#pragma unroll
            for (int jj = 0; jj < 4; ++jj) {
                int j = i * 4 + jj;
                float4 q = s_w4[htid * 32 + (j & ~7) + ((j & 7) ^ (htid & 7))];
                wv[jj * 4 + 0] = q.x; wv[jj * 4 + 1] = q.y;
                wv[jj * 4 + 2] = q.z; wv[jj * 4 + 3] = q.w;
            }
#pragma unroll
            for (int g = 0; g < GPOS; ++g) {
                float t = sxbase[i * 32 + g * 256];
#pragma unroll
                for (int c = 0; c < 16; ++c) pr[g][c] = fmaf(t, wv[c], pr[g][c]);
            }
        }

        // ---- dynamic routing (per half, per position g)
#pragma unroll 1
        for (int g = 0; g < GPOS; ++g) {
            float logit = 0.0f;
            float outv  = 0.0f;
            float* s_lastred;

#pragma unroll
            for (int it = 0; it < 3; ++it) {
                float e = (it == 0) ? 1.0f : __expf(logit);   // shift-free

                float y[16];
#pragma unroll
                for (int c = 0; c < 16; ++c) y[c] = e * pr[g][c];
                float z = e;
#pragma unroll
                for (int off = 16; off; off >>= 1)
                    z += __shfl_xor_sync(0xffffffffu, z, off);

                // reduce-scatter butterfly: 16 comps -> lane pairs
#pragma unroll
                for (int c = 0; c < 8; ++c) {
                    float snd = (lane & 16) ? y[c] : y[c + 8];
                    float rcv = __shfl_xor_sync(0xffffffffu, snd, 16);
                    y[c] = ((lane & 16) ? y[c + 8] : y[c]) + rcv;
                }
#pragma unroll
                for (int c = 0; c < 4; ++c) {
                    float snd = (lane & 8) ? y[c] : y[c + 4];
                    float rcv = __shfl_xor_sync(0xffffffffu, snd, 8);
                    y[c] = ((lane & 8) ? y[c + 4] : y[c]) + rcv;
                }
#pragma unroll
                for (int c = 0; c < 2; ++c) {
                    float snd = (lane & 4) ? y[c] : y[c + 2];
                    float rcv = __shfl_xor_sync(0xffffffffu, snd, 4);
                    y[c] = ((lane & 4) ? y[c + 2] : y[c]) + rcv;
                }
                {
                    float snd = (lane & 2) ? y[0] : y[1];
                    float rcv = __shfl_xor_sync(0xffffffffu, snd, 2);
                    y[0] = ((lane & 2) ? y[1] : y[0]) + rcv;
                }
                y[0] += __shfl_xor_sync(0xffffffffu, y[0], 1);
                // lane l holds warp-sum of comp (l>>1)&15; all lanes have z

                float* s_partb = s_part_h + pb * (2 * NWARP * 17);
                float* s_redb  = s_red_h  + pb * (2 * 17);
                // no pre-write sync needed: this buffer's last readers
                // finished two barriers ago (double buffering)
                if (!(lane & 1)) s_partb[wh * 17 + ((lane >> 1) & 15)] = y[0];
                if (lane == 1)   s_partb[wh * 17 + 16] = z;
                __syncthreads();
                if (htid < 17) {
                    float a = 0.0f;
#pragma unroll
                    for (int wq = 0; wq < NWARP; ++wq) a += s_partb[wq * 17 + htid];
                    s_redb[htid] = a;
                }
                __syncthreads();

                // normalize + squash + logit update, registers only
                float Z    = s_redb[16];
                float invZ = __fdividef(1.0f, Z);
                float sq = 0.0f, d = 0.0f;
#pragma unroll
                for (int c = 0; c < 16; ++c) {
                    float v = s_redb[c];             // unnormalized s-hat
                    sq = fmaf(v, v, sq);
                    d  = fmaf(pr[g][c], v, d);
                }
                sq *= invZ * invZ;
                float scale = __fdividef(sqrtf(sq), 1.0f + sq);
                if (it < 2) logit += scale * (d * invZ);
                else      { outv  = scale * invZ; s_lastred = s_redb; }
                pb ^= 1;
            }

            if (htid < 16) s_outh[htid * GPOS + g] = s_lastred[htid] * outv;
        }

        __syncthreads();                             // s_out ready
        // ---- output: 64 threads/half, 16 rows x 4 contiguous floats
        if (htid < 16 * GPOS) {
            int c = htid >> 2;
            int g = htid & 3;
            out[(((size_t)b * 512 + o * 16 + c) * 12 + oh) * 12 + (ow0 + g)]
                = s_outh[c * GPOS + g];
        }
        // next itg's x staging writes s_x only; routing syncs above already
        // separate it from this itg's s_x readers
    }
}

extern "C" void kernel_launch(void* const* d_in, const int* in_sizes, int n_in,
                              void* d_out, int out_size)
{
    const float* x = (const float*)d_in[0];
    const float* w = (const float*)d_in[1];
    if (n_in >= 2 && in_sizes[0] == 32 * 288 * 8 * 16 && in_sizes[1] == 4 * 256 * 14 * 14) {
        x = (const float*)d_in[1];
        w = (const float*)d_in[0];
    }
    const int smem_bytes = (288 * 32 * 4 + 2 * 4608 + 2 * 2 * NWARP * 17
                            + 2 * 2 * 17 + 2 * 64) * (int)sizeof(float);
    cudaFuncSetAttribute(caps_route_kernel,
                         cudaFuncAttributeMaxDynamicSharedMemorySize, smem_bytes);
    dim3 grid(9, 32);   // (position chunk) x (out capsule)
    caps_route_kernel<<<grid, NTHR, smem_bytes>>>(x, w, (float*)d_out);
}

// round 11
// speedup vs baseline: 1.9006x; 1.1860x over previous
#include <cuda_runtime.h>
#include <math.h>

// CapsuleLayer dynamic routing, fully fused, weight-slab resident in SMEM.
//   x: (4,256,14,14) f32   weight: (32,288,8,16) f32   out: (4,512,12,12) f32
// Grid (9,32): CTA = (16 position-groups, output capsule o). 576 threads =
// two 288-thread halves; each half owns one 4-position group per outer iter.
// Weights staged once per CTA (coalesced LDG, swizzled conflict-free STS/LDS).
// Routing: shift-free softmax, positions reduced in PAIRS through one merged
// butterfly: offset-1 exchange splits the pair across lane parity (even lanes
// carry g_even, odd g_odd), then offsets 2/4/8/16 reduce-scatter 16 comps
// 16->8->4->2->1 within each parity class. 6 reduction rounds, 14 syncs/itg.

#define GPOS 4
#define HALF_THR 288
#define NTHR 576
#define NWARP 9
#define GROUPS_PER_CHUNK 16
#define ITERS_PER_CTA 8

__global__ __launch_bounds__(NTHR, 1)
void caps_route_kernel(const float* __restrict__ x,
                       const float* __restrict__ w,
                       float* __restrict__ out)
{
    extern __shared__ float smem[];
    float4* s_w4   = (float4*)smem;                  // 288*32 float4 = 147456 B
    float*  s_x    = smem + 288 * 32 * 4;            // 2 halves * 4608
    float*  s_part = s_x + 2 * 4608;                 // 2 halves * 9 * 36
    float*  s_red  = s_part + 2 * NWARP * 36;        // 2 halves * 36
    float*  s_out  = s_red + 2 * 36;                 // 2 halves * 64

    const int tid  = threadIdx.x;
    const int h    = (tid >= HALF_THR) ? 1 : 0;
    const int htid = tid - h * HALF_THR;             // 0..287 == route k
    const int lane = tid & 31;
    const int wh   = htid >> 5;                      // warp-in-half == kk

    float* s_xh    = s_x    + h * 4608;
    float* s_parth = s_part + h * NWARP * 36;
    float* s_redh  = s_red  + h * 36;
    float* s_outh  = s_out  + h * 64;

    const int o = blockIdx.y;

    // ---- stage full weight slab for o (147 KB), once per CTA
    {
        const float4* wbase = (const float4*)(w + (size_t)o * 288 * 128);
#pragma unroll
        for (int pass = 0; pass < 16; ++pass) {
            int idx = tid + pass * NTHR;             // warp reads one k, j=lane
            int k = idx >> 5;
            int j = idx & 31;
            s_w4[k * 32 + (j & ~7) + ((j & 7) ^ (k & 7))] = wbase[idx];
        }
    }

    // ---- strength-reduced x-staging constants (288 = 16*18)
    const int c0  = htid / 18;                       // 0..15
    const int rr  = htid - c0 * 18;                  // 0..17
    const int khh = rr / 6;
    const int ww  = rr - khh * 6;
    const int kh  = wh / 3;
    const int kw  = wh - 3 * kh;
    const float* sxbase = s_xh + (kh * 6 + kw) * 256 + lane;   // lane == inc
    float* sxw = s_xh + (khh * 6 + ww) * 256 + (c0 & 7) * 32 + (c0 >> 3);

    // lane -> (parity, component) after the merged butterfly:
    // at each halving step the bit-SET lane keeps the UPPER block, so
    // comp = 8*bit1 + 4*bit2 + 2*bit3 + 1*bit4
    const int par  = lane & 1;
    const int comp = ((lane & 2) ? 8 : 0) | ((lane & 4) ? 4 : 0)
                   | ((lane & 8) ? 2 : 0) | ((lane & 16) ? 1 : 0);
    const int sp_addr = wh * 36 + par * 17 + comp;

#pragma unroll 1
    for (int itg = 0; itg < ITERS_PER_CTA; ++itg) {
        const int nb  = blockIdx.x * GROUPS_PER_CHUNK + itg * 2 + h;
        const int b   = nb / 36;
        const int r   = nb - b * 36;
        const int oh  = r / 3;
        const int ow0 = (r - oh * 3) * GPOS;

        // ---- stage x patch (per half); indices pass-invariant
        {
            const float* xsrc = x + ((size_t)b * 256 + c0) * 196
                                  + (oh + khh) * 14 + ow0 + ww;
#pragma unroll
            for (int pass = 0; pass < 16; ++pass)
                sxw[pass * 2] = xsrc[pass * 3136];
        }
        __syncthreads();                             // x ready (+ weights, itg=0)

        // ---- priors: pr[g][c] = sum_i x[g][k][i] * w[o][k][i][c]
        float pr[GPOS][16];
#pragma unroll
        for (int g = 0; g < GPOS; ++g)
#pragma unroll
            for (int c = 0; c < 16; ++c) pr[g][c] = 0.0f;

#pragma unroll
        for (int i = 0; i < 8; ++i) {
            float wv[16];
#pragma unroll
            for (int jj = 0; jj < 4; ++jj) {
                int j = i * 4 + jj;
                float4 q = s_w4[htid * 32 + (j & ~7) + ((j & 7) ^ (htid & 7))];
                wv[jj * 4 + 0] = q.x; wv[jj * 4 + 1] = q.y;
                wv[jj * 4 + 2] = q.z; wv[jj * 4 + 3] = q.w;
            }
#pragma unroll
            for (int g = 0; g < GPOS; ++g) {
                float t = sxbase[i * 32 + g * 256];
#pragma unroll
                for (int c = 0; c < 16; ++c) pr[g][c] = fmaf(t, wv[c], pr[g][c]);
            }
        }

        // ---- dynamic routing: 3 iterations, positions reduced in pairs
        float logit[GPOS] = {0.0f, 0.0f, 0.0f, 0.0f};

#pragma unroll
        for (int it = 0; it < 3; ++it) {
#pragma unroll
            for (int p = 0; p < 2; ++p) {
                const int ga = 2 * p, gb = 2 * p + 1;
                float ea = (it == 0) ? 1.0f : __expf(logit[ga]);
                float eb = (it == 0) ? 1.0f : __expf(logit[gb]);

                // offset 1: parity split (even lanes: ga, odd lanes: gb)
                float ym[16];
#pragma unroll
                for (int c = 0; c < 16; ++c) {
                    float a   = ea * pr[ga][c];
                    float bq  = eb * pr[gb][c];
                    float snd = par ? a : bq;
                    float rcv = __shfl_xor_sync(0xffffffffu, snd, 1);
                    ym[c] = (par ? bq : a) + rcv;
                }
                float zm;
                {
                    float snd = par ? ea : eb;
                    float rcv = __shfl_xor_sync(0xffffffffu, snd, 1);
                    zm = (par ? eb : ea) + rcv;
                }
                // offset 2: 16 -> 8
#pragma unroll
                for (int c = 0; c < 8; ++c) {
                    float snd = (lane & 2) ? ym[c] : ym[c + 8];
                    float rcv = __shfl_xor_sync(0xffffffffu, snd, 2);
                    ym[c] = ((lane & 2) ? ym[c + 8] : ym[c]) + rcv;
                }
                // offset 4: 8 -> 4
#pragma unroll
                for (int c = 0; c < 4; ++c) {
                    float snd = (lane & 4) ? ym[c] : ym[c + 4];
                    float rcv = __shfl_xor_sync(0xffffffffu, snd, 4);
                    ym[c] = ((lane & 4) ? ym[c + 4] : ym[c]) + rcv;
                }
                // offset 8: 4 -> 2
#pragma unroll
                for (int c = 0; c < 2; ++c) {
                    float snd = (lane & 8) ? ym[c] : ym[c + 2];
                    float rcv = __shfl_xor_sync(0xffffffffu, snd, 8);
                    ym[c] = ((lane & 8) ? ym[c + 2] : ym[c]) + rcv;
                }
                // offset 16: 2 -> 1
                {
                    float snd = (lane & 16) ? ym[0] : ym[1];
                    float rcv = __shfl_xor_sync(0xffffffffu, snd, 16);
                    ym[0] = ((lane & 16) ? ym[1] : ym[0]) + rcv;
                }
                zm += __shfl_xor_sync(0xffffffffu, zm, 2);
                zm += __shfl_xor_sync(0xffffffffu, zm, 4);
                zm += __shfl_xor_sync(0xffffffffu, zm, 8);
                zm += __shfl_xor_sync(0xffffffffu, zm, 16);

                s_parth[sp_addr] = ym[0];            // all 32 lanes distinct
                if (lane < 2) s_parth[wh * 36 + par * 17 + 16] = zm;
                __syncthreads();
                if (htid < 34) {
                    float a = 0.0f;
#pragma unroll
                    for (int wq = 0; wq < NWARP; ++wq)
                        a += s_parth[wq * 36 + htid];
                    s_redh[htid] = a;
                }
                __syncthreads();

                // normalize + squash + update for both positions (registers)
                float Za = s_redh[16], Zb = s_redh[33];
                float iZa = __fdividef(1.0f, Za);
                float iZb = __fdividef(1.0f, Zb);
                float sqa = 0.0f, da = 0.0f, sqb = 0.0f, db = 0.0f;
#pragma unroll
                for (int c = 0; c < 16; ++c) {
                    float va = s_redh[c];
                    float vb = s_redh[17 + c];
                    sqa = fmaf(va, va, sqa);  da = fmaf(pr[ga][c], va, da);
                    sqb = fmaf(vb, vb, sqb);  db = fmaf(pr[gb][c], vb, db);
                }
                sqa *= iZa * iZa;  sqb *= iZb * iZb;
                float sca = __fdividef(sqrtf(sqa), 1.0f + sqa);
                float scb = __fdividef(sqrtf(sqb), 1.0f + sqb);
                if (it < 2) {
                    logit[ga] += sca * (da * iZa);
                    logit[gb] += scb * (db * iZb);
                } else {
                    float ova = sca * iZa, ovb = scb * iZb;
                    if (htid < 16) {
                        s_outh[htid * GPOS + ga] = s_redh[htid]      * ova;
                        s_outh[htid * GPOS + gb] = s_redh[17 + htid] * ovb;
                    }
                }
            }
        }

        __syncthreads();                             // s_out ready
        // ---- output: 64 threads/half, 16 rows x 4 contiguous floats
        if (htid < 16 * GPOS) {
            int c = htid >> 2;
            int g = htid & 3;
            out[(((size_t)b * 512 + o * 16 + c) * 12 + oh) * 12 + (ow0 + g)]
                = s_outh[c * GPOS + g];
        }
    }
}

extern "C" void kernel_launch(void* const* d_in, const int* in_sizes, int n_in,
                              void* d_out, int out_size)
{
    const float* x = (const float*)d_in[0];
    const float* w = (const float*)d_in[1];
    if (n_in >= 2 && in_sizes[0] == 32 * 288 * 8 * 16 && in_sizes[1] == 4 * 256 * 14 * 14) {
        x = (const float*)d_in[1];
        w = (const float*)d_in[0];
    }
    const int smem_bytes = (288 * 32 * 4 + 2 * 4608 + 2 * NWARP * 36
                            + 2 * 36 + 2 * 64) * (int)sizeof(float);
    cudaFuncSetAttribute(caps_route_kernel,
                         cudaFuncAttributeMaxDynamicSharedMemorySize, smem_bytes);
    dim3 grid(9, 32);   // (position chunk) x (out capsule)
    caps_route_kernel<<<grid, NTHR, smem_bytes>>>(x, w, (float*)d_out);
}

// round 12
// speedup vs baseline: 2.6004x; 1.3682x over previous
#include <cuda_runtime.h>
#include <math.h>

// CapsuleLayer dynamic routing, fully fused, weight-slab resident in SMEM.
//   x: (4,256,14,14) f32   weight: (32,288,8,16) f32   out: (4,512,12,12) f32
// Grid (9,32): CTA = (16 position-groups, output capsule o). 576 threads =
// two 288-thread halves; each half owns one 4-position group per outer iter.
// Weights staged once per CTA (coalesced LDG, swizzled conflict-free STS/LDS).
// x patch stored with PADDED stride 257 so staging STS is bank-conflict-free
// (256 made every staging store a 32-way conflict = the R11 L1 bottleneck).
// Routing: shift-free softmax, positions reduced in PAIRS in one butterfly.

#define GPOS 4
#define HALF_THR 288
#define NTHR 576
#define NWARP 9
#define GROUPS_PER_CHUNK 16
#define ITERS_PER_CTA 8
#define XSTRIDE 257            // 18 positions * 257 floats, pad kills conflicts
#define XHALF (18 * XSTRIDE)

__global__ __launch_bounds__(NTHR, 1)
void caps_route_kernel(const float* __restrict__ x,
                       const float* __restrict__ w,
                       float* __restrict__ out)
{
    extern __shared__ float smem[];
    float4* s_w4   = (float4*)smem;                  // 288*32 float4 = 147456 B
    float*  s_x    = smem + 288 * 32 * 4;            // 2 halves * XHALF
    float*  s_part = s_x + 2 * XHALF;                // 2 halves * 9 * 36
    float*  s_red  = s_part + 2 * NWARP * 36;        // 2 halves * 36
    float*  s_out  = s_red + 2 * 36;                 // 2 halves * 64

    const int tid  = threadIdx.x;
    const int h    = (tid >= HALF_THR) ? 1 : 0;
    const int htid = tid - h * HALF_THR;             // 0..287 == route k
    const int lane = tid & 31;
    const int wh   = htid >> 5;                      // warp-in-half == kk

    float* s_xh    = s_x    + h * XHALF;
    float* s_parth = s_part + h * NWARP * 36;
    float* s_redh  = s_red  + h * 36;
    float* s_outh  = s_out  + h * 64;

    const int o = blockIdx.y;

    // ---- stage full weight slab for o (147 KB), once per CTA
    {
        const float4* wbase = (const float4*)(w + (size_t)o * 288 * 128);
#pragma unroll
        for (int pass = 0; pass < 16; ++pass) {
            int idx = tid + pass * NTHR;             // warp reads one k, j=lane
            int k = idx >> 5;
            int j = idx & 31;
            s_w4[k * 32 + (j & ~7) + ((j & 7) ^ (k & 7))] = wbase[idx];
        }
    }

    // ---- strength-reduced x-staging constants (288 = 16*18)
    const int c0  = htid / 18;                       // 0..15
    const int rr  = htid - c0 * 18;                  // 0..17 == position
    const int khh = rr / 6;
    const int ww  = rr - khh * 6;
    const int kh  = wh / 3;
    const int kw  = wh - 3 * kh;
    const float* sxbase = s_xh + (kh * 6 + kw) * XSTRIDE + lane;  // lane == inc
    float* sxw = s_xh + rr * XSTRIDE + (c0 & 7) * 32 + (c0 >> 3);

    // lane -> (parity, component) after the merged butterfly
    const int par  = lane & 1;
    const int comp = ((lane & 2) ? 8 : 0) | ((lane & 4) ? 4 : 0)
                   | ((lane & 8) ? 2 : 0) | ((lane & 16) ? 1 : 0);
    const int sp_addr = wh * 36 + par * 17 + comp;

#pragma unroll 1
    for (int itg = 0; itg < ITERS_PER_CTA; ++itg) {
        const int nb  = blockIdx.x * GROUPS_PER_CHUNK + itg * 2 + h;
        const int b   = nb / 36;
        const int r   = nb - b * 36;
        const int oh  = r / 3;
        const int ow0 = (r - oh * 3) * GPOS;

        // ---- stage x patch (per half); conflict-free STS via padded stride
        {
            const float* xsrc = x + ((size_t)b * 256 + c0) * 196
                                  + (oh + khh) * 14 + ow0 + ww;
#pragma unroll
            for (int pass = 0; pass < 16; ++pass)
                sxw[pass * 2] = xsrc[pass * 3136];
        }
        __syncthreads();                             // x ready (+ weights, itg=0)

        // ---- priors: pr[g][c] = sum_i x[g][k][i] * w[o][k][i][c]
        float pr[GPOS][16];
#pragma unroll
        for (int g = 0; g < GPOS; ++g)
#pragma unroll
            for (int c = 0; c < 16; ++c) pr[g][c] = 0.0f;

#pragma unroll
        for (int i = 0; i < 8; ++i) {
            float wv[16];
#pragma unroll
            for (int jj = 0; jj < 4; ++jj) {
                int j = i * 4 + jj;
                float4 q = s_w4[htid * 32 + (j & ~7) + ((j & 7) ^ (htid & 7))];
                wv[jj * 4 + 0] = q.x; wv[jj * 4 + 1] = q.y;
                wv[jj * 4 + 2] = q.z; wv[jj * 4 + 3] = q.w;
            }
#pragma unroll
            for (int g = 0; g < GPOS; ++g) {
                float t = sxbase[i * 32 + g * XSTRIDE];
#pragma unroll
                for (int c = 0; c < 16; ++c) pr[g][c] = fmaf(t, wv[c], pr[g][c]);
            }
        }

        // ---- dynamic routing: 3 iterations, positions reduced in pairs
        float logit[GPOS] = {0.0f, 0.0f, 0.0f, 0.0f};

#pragma unroll
        for (int it = 0; it < 3; ++it) {
#pragma unroll
            for (int p = 0; p < 2; ++p) {
                const int ga = 2 * p, gb = 2 * p + 1;
                float ea = (it == 0) ? 1.0f : __expf(logit[ga]);
                float eb = (it == 0) ? 1.0f : __expf(logit[gb]);

                // offset 1: parity split (even lanes: ga, odd lanes: gb)
                float ym[16];
#pragma unroll
                for (int c = 0; c < 16; ++c) {
                    float a   = ea * pr[ga][c];
                    float bq  = eb * pr[gb][c];
                    float snd = par ? a : bq;
                    float rcv = __shfl_xor_sync(0xffffffffu, snd, 1);
                    ym[c] = (par ? bq : a) + rcv;
                }
                float zm;
                {
                    float snd = par ? ea : eb;
                    float rcv = __shfl_xor_sync(0xffffffffu, snd, 1);
                    zm = (par ? eb : ea) + rcv;
                }
                // offset 2: 16 -> 8
#pragma unroll
                for (int c = 0; c < 8; ++c) {
                    float snd = (lane & 2) ? ym[c] : ym[c + 8];
                    float rcv = __shfl_xor_sync(0xffffffffu, snd, 2);
                    ym[c] = ((lane & 2) ? ym[c + 8] : ym[c]) + rcv;
                }
                // offset 4: 8 -> 4
#pragma unroll
                for (int c = 0; c < 4; ++c) {
                    float snd = (lane & 4) ? ym[c] : ym[c + 4];
                    float rcv = __shfl_xor_sync(0xffffffffu, snd, 4);
                    ym[c] = ((lane & 4) ? ym[c + 4] : ym[c]) + rcv;
                }
                // offset 8: 4 -> 2
#pragma unroll
                for (int c = 0; c < 2; ++c) {
                    float snd = (lane & 8) ? ym[c] : ym[c + 2];
                    float rcv = __shfl_xor_sync(0xffffffffu, snd, 8);
                    ym[c] = ((lane & 8) ? ym[c + 2] : ym[c]) + rcv;
                }
                // offset 16: 2 -> 1
                {
                    float snd = (lane & 16) ? ym[0] : ym[1];
                    float rcv = __shfl_xor_sync(0xffffffffu, snd, 16);
                    ym[0] = ((lane & 16) ? ym[1] : ym[0]) + rcv;
                }
                zm += __shfl_xor_sync(0xffffffffu, zm, 2);
                zm += __shfl_xor_sync(0xffffffffu, zm, 4);
                zm += __shfl_xor_sync(0xffffffffu, zm, 8);
                zm += __shfl_xor_sync(0xffffffffu, zm, 16);

                s_parth[sp_addr] = ym[0];            // all 32 lanes distinct
                if (lane < 2) s_parth[wh * 36 + par * 17 + 16] = zm;
                __syncthreads();
                if (htid < 34) {
                    float a = 0.0f;
#pragma unroll
                    for (int wq = 0; wq < NWARP; ++wq)
                        a += s_parth[wq * 36 + htid];
                    s_redh[htid] = a;
                }
                __syncthreads();

                // normalize + squash + update for both positions (registers)
                float Za = s_redh[16], Zb = s_redh[33];
                float iZa = __fdividef(1.0f, Za);
                float iZb = __fdividef(1.0f, Zb);
                float sqa = 0.0f, da = 0.0f, sqb = 0.0f, db = 0.0f;
#pragma unroll
                for (int c = 0; c < 16; ++c) {
                    float va = s_redh[c];
                    float vb = s_redh[17 + c];
                    sqa = fmaf(va, va, sqa);  da = fmaf(pr[ga][c], va, da);
                    sqb = fmaf(vb, vb, sqb);  db = fmaf(pr[gb][c], vb, db);
                }
                sqa *= iZa * iZa;  sqb *= iZb * iZb;
                float sca = __fdividef(sqrtf(sqa), 1.0f + sqa);
                float scb = __fdividef(sqrtf(sqb), 1.0f + sqb);
                if (it < 2) {
                    logit[ga] += sca * (da * iZa);
                    logit[gb] += scb * (db * iZb);
                } else {
                    float ova = sca * iZa, ovb = scb * iZb;
                    if (htid < 16) {
                        s_outh[htid * GPOS + ga] = s_redh[htid]      * ova;
                        s_outh[htid * GPOS + gb] = s_redh[17 + htid] * ovb;
                    }
                }
            }
        }

        __syncthreads();                             // s_out ready
        // ---- output: 64 threads/half, 16 rows x 4 contiguous floats
        if (htid < 16 * GPOS) {
            int c = htid >> 2;
            int g = htid & 3;
            out[(((size_t)b * 512 + o * 16 + c) * 12 + oh) * 12 + (ow0 + g)]
                = s_outh[c * GPOS + g];
        }
    }
}

extern "C" void kernel_launch(void* const* d_in, const int* in_sizes, int n_in,
                              void* d_out, int out_size)
{
    const float* x = (const float*)d_in[0];
    const float* w = (const float*)d_in[1];
    if (n_in >= 2 && in_sizes[0] == 32 * 288 * 8 * 16 && in_sizes[1] == 4 * 256 * 14 * 14) {
        x = (const float*)d_in[1];
        w = (const float*)d_in[0];
    }
    const int smem_bytes = (288 * 32 * 4 + 2 * XHALF + 2 * NWARP * 36
                            + 2 * 36 + 2 * 64) * (int)sizeof(float);
    cudaFuncSetAttribute(caps_route_kernel,
                         cudaFuncAttributeMaxDynamicSharedMemorySize, smem_bytes);
    dim3 grid(9, 32);   // (position chunk) x (out capsule)
    caps_route_kernel<<<grid, NTHR, smem_bytes>>>(x, w, (float*)d_out);
}

// round 13
// speedup vs baseline: 2.6116x; 1.0043x over previous
#include <cuda_runtime.h>
#include <math.h>

// CapsuleLayer dynamic routing, fully fused, weight-slab resident in SMEM.
//   x: (4,256,14,14) f32   weight: (32,288,8,16) f32   out: (4,512,12,12) f32
// Grid (9,32): CTA = (16 position-groups, output capsule o). 576 threads =
// two 288-thread halves; each half owns one 4-position group per outer iter.
// Weights staged once per CTA (coalesced LDG, swizzled conflict-free STS/LDS).
// x patch stored with padded stride 257 (conflict-free staging STS).
// Routing: shift-free softmax; the two position-PAIRS of a half run their
// merged butterflies back-to-back into separate s_part regions, sharing ONE
// barrier pair per routing iteration (8 syncs/itg). it=0 is specialized
// (e==1, Z==288: no e-mul, no z reduction).

#define GPOS 4
#define HALF_THR 288
#define NTHR 576
#define NWARP 9
#define GROUPS_PER_CHUNK 16
#define ITERS_PER_CTA 8
#define XSTRIDE 257
#define XHALF (18 * XSTRIDE)
#define PWIDTH 68              // per-warp partials: 2 pairs * 2 par * 17

__global__ __launch_bounds__(NTHR, 1)
void caps_route_kernel(const float* __restrict__ x,
                       const float* __restrict__ w,
                       float* __restrict__ out)
{
    extern __shared__ float smem[];
    float4* s_w4   = (float4*)smem;                  // 288*32 float4 = 147456 B
    float*  s_x    = smem + 288 * 32 * 4;            // 2 halves * XHALF
    float*  s_part = s_x + 2 * XHALF;                // 2 halves * 9 * 68
    float*  s_red  = s_part + 2 * NWARP * PWIDTH;    // 2 halves * 68
    float*  s_out  = s_red + 2 * PWIDTH;             // 2 halves * 64

    const int tid  = threadIdx.x;
    const int h    = (tid >= HALF_THR) ? 1 : 0;
    const int htid = tid - h * HALF_THR;             // 0..287 == route k
    const int lane = tid & 31;
    const int wh   = htid >> 5;                      // warp-in-half == kk

    float* s_xh    = s_x    + h * XHALF;
    float* s_parth = s_part + h * NWARP * PWIDTH;
    float* s_redh  = s_red  + h * PWIDTH;
    float* s_outh  = s_out  + h * 64;

    const int o = blockIdx.y;

    // ---- stage full weight slab for o (147 KB), once per CTA
    {
        const float4* wbase = (const float4*)(w + (size_t)o * 288 * 128);
#pragma unroll
        for (int pass = 0; pass < 16; ++pass) {
            int idx = tid + pass * NTHR;             // warp reads one k, j=lane
            int k = idx >> 5;
            int j = idx & 31;
            s_w4[k * 32 + (j & ~7) + ((j & 7) ^ (k & 7))] = wbase[idx];
        }
    }

    // ---- strength-reduced x-staging constants (288 = 16*18)
    const int c0  = htid / 18;                       // 0..15
    const int rr  = htid - c0 * 18;                  // 0..17 == position
    const int khh = rr / 6;
    const int ww  = rr - khh * 6;
    const int kh  = wh / 3;
    const int kw  = wh - 3 * kh;
    const float* sxbase = s_xh + (kh * 6 + kw) * XSTRIDE + lane;  // lane == inc
    float* sxw = s_xh + rr * XSTRIDE + (c0 & 7) * 32 + (c0 >> 3);

    // lane -> (parity, component) after the merged butterfly:
    // at each halving step the bit-SET lane keeps the UPPER block, so
    // comp = 8*bit1 + 4*bit2 + 2*bit3 + 1*bit4
    const int par  = lane & 1;
    const int comp = ((lane & 2) ? 8 : 0) | ((lane & 4) ? 4 : 0)
                   | ((lane & 8) ? 2 : 0) | ((lane & 16) ? 1 : 0);
    const int sp_base = wh * PWIDTH + par * 17;      // + pair*34 (+comp / +16)

#pragma unroll 1
    for (int itg = 0; itg < ITERS_PER_CTA; ++itg) {
        const int nb  = blockIdx.x * GROUPS_PER_CHUNK + itg * 2 + h;
        const int b   = nb / 36;
        const int r   = nb - b * 36;
        const int oh  = r / 3;
        const int ow0 = (r - oh * 3) * GPOS;

        // ---- stage x patch (per half); conflict-free STS via padded stride
        {
            const float* xsrc = x + ((size_t)b * 256 + c0) * 196
                                  + (oh + khh) * 14 + ow0 + ww;
#pragma unroll
            for (int pass = 0; pass < 16; ++pass)
                sxw[pass * 2] = xsrc[pass * 3136];
        }
        __syncthreads();                             // x ready (+ weights, itg=0)

        // ---- priors: pr[g][c] = sum_i x[g][k][i] * w[o][k][i][c]
        float pr[GPOS][16];
#pragma unroll
        for (int g = 0; g < GPOS; ++g)
#pragma unroll
            for (int c = 0; c < 16; ++c) pr[g][c] = 0.0f;

#pragma unroll
        for (int i = 0; i < 8; ++i) {
            float wv[16];
#pragma unroll
            for (int jj = 0; jj < 4; ++jj) {
                int j = i * 4 + jj;
                float4 q = s_w4[htid * 32 + (j & ~7) + ((j & 7) ^ (htid & 7))];
                wv[jj * 4 + 0] = q.x; wv[jj * 4 + 1] = q.y;
                wv[jj * 4 + 2] = q.z; wv[jj * 4 + 3] = q.w;
            }
#pragma unroll
            for (int g = 0; g < GPOS; ++g) {
                float t = sxbase[i * 32 + g * XSTRIDE];
#pragma unroll
                for (int c = 0; c < 16; ++c) pr[g][c] = fmaf(t, wv[c], pr[g][c]);
            }
        }

        // ---- dynamic routing: 3 iterations; both pairs share one barrier set
        float logit[GPOS] = {0.0f, 0.0f, 0.0f, 0.0f};

#pragma unroll
        for (int it = 0; it < 3; ++it) {
#pragma unroll
            for (int p = 0; p < 2; ++p) {
                const int ga = 2 * p, gb = 2 * p + 1;
                float ym[16];
                float zm = 0.0f;

                if (it == 0) {
                    // e == 1: parity split of raw priors, Z known (=288)
#pragma unroll
                    for (int c = 0; c < 16; ++c) {
                        float a   = pr[ga][c];
                        float bq  = pr[gb][c];
                        float snd = par ? a : bq;
                        float rcv = __shfl_xor_sync(0xffffffffu, snd, 1);
                        ym[c] = (par ? bq : a) + rcv;
                    }
                } else {
                    float ea = __expf(logit[ga]);
                    float eb = __expf(logit[gb]);
#pragma unroll
                    for (int c = 0; c < 16; ++c) {
                        float a   = ea * pr[ga][c];
                        float bq  = eb * pr[gb][c];
                        float snd = par ? a : bq;
                        float rcv = __shfl_xor_sync(0xffffffffu, snd, 1);
                        ym[c] = (par ? bq : a) + rcv;
                    }
                    {
                        float snd = par ? ea : eb;
                        float rcv = __shfl_xor_sync(0xffffffffu, snd, 1);
                        zm = (par ? eb : ea) + rcv;
                    }
                }
                // offset 2: 16 -> 8
#pragma unroll
                for (int c = 0; c < 8; ++c) {
                    float snd = (lane & 2) ? ym[c] : ym[c + 8];
                    float rcv = __shfl_xor_sync(0xffffffffu, snd, 2);
                    ym[c] = ((lane & 2) ? ym[c + 8] : ym[c]) + rcv;
                }
                // offset 4: 8 -> 4
#pragma unroll
                for (int c = 0; c < 4; ++c) {
                    float snd = (lane & 4) ? ym[c] : ym[c + 4];
                    float rcv = __shfl_xor_sync(0xffffffffu, snd, 4);
                    ym[c] = ((lane & 4) ? ym[c + 4] : ym[c]) + rcv;
                }
                // offset 8: 4 -> 2
#pragma unroll
                for (int c = 0; c < 2; ++c) {
                    float snd = (lane & 8) ? ym[c] : ym[c + 2];
                    float rcv = __shfl_xor_sync(0xffffffffu, snd, 8);
                    ym[c] = ((lane & 8) ? ym[c + 2] : ym[c]) + rcv;
                }
                // offset 16: 2 -> 1
                {
                    float snd = (lane & 16) ? ym[0] : ym[1];
                    float rcv = __shfl_xor_sync(0xffffffffu, snd, 16);
                    ym[0] = ((lane & 16) ? ym[1] : ym[0]) + rcv;
                }
                if (it != 0) {
                    zm += __shfl_xor_sync(0xffffffffu, zm, 2);
                    zm += __shfl_xor_sync(0xffffffffu, zm, 4);
                    zm += __shfl_xor_sync(0xffffffffu, zm, 8);
                    zm += __shfl_xor_sync(0xffffffffu, zm, 16);
                }

                s_parth[sp_base + p * 34 + comp] = ym[0];
                if (it != 0 && lane < 2) s_parth[sp_base + p * 34 + 16] = zm;
            }
            __syncthreads();
            if (htid < PWIDTH) {
                float a = 0.0f;
#pragma unroll
                for (int wq = 0; wq < NWARP; ++wq)
                    a += s_parth[wq * PWIDTH + htid];
                s_redh[htid] = a;
            }
            __syncthreads();

            // epilogue for all 4 positions (registers + broadcast LDS)
#pragma unroll
            for (int p = 0; p < 2; ++p) {
                const int ga = 2 * p, gb = 2 * p + 1;
                float Za = (it == 0) ? 288.0f : s_redh[p * 34 + 16];
                float Zb = (it == 0) ? 288.0f : s_redh[p * 34 + 33];
                float iZa = __fdividef(1.0f, Za);
                float iZb = __fdividef(1.0f, Zb);
                float sqa = 0.0f, da = 0.0f, sqb = 0.0f, db = 0.0f;
#pragma unroll
                for (int c = 0; c < 16; ++c) {
                    float va = s_redh[p * 34 + c];
                    float vb = s_redh[p * 34 + 17 + c];
                    sqa = fmaf(va, va, sqa);  da = fmaf(pr[ga][c], va, da);
                    sqb = fmaf(vb, vb, sqb);  db = fmaf(pr[gb][c], vb, db);
                }
                sqa *= iZa * iZa;  sqb *= iZb * iZb;
                float sca = __fdividef(sqrtf(sqa), 1.0f + sqa);
                float scb = __fdividef(sqrtf(sqb), 1.0f + sqb);
                if (it < 2) {
                    logit[ga] += sca * (da * iZa);
                    logit[gb] += scb * (db * iZb);
                } else {
                    float ova = sca * iZa, ovb = scb * iZb;
                    if (htid < 16) {
                        s_outh[htid * GPOS + ga] = s_redh[p * 34 + htid]      * ova;
                        s_outh[htid * GPOS + gb] = s_redh[p * 34 + 17 + htid] * ovb;
                    }
                }
            }
        }

        __syncthreads();                             // s_out ready
        // ---- output: 64 threads/half, 16 rows x 4 contiguous floats
        if (htid < 16 * GPOS) {
            int c = htid >> 2;
            int g = htid & 3;
            out[(((size_t)b * 512 + o * 16 + c) * 12 + oh) * 12 + (ow0 + g)]
                = s_outh[c * GPOS + g];
        }
    }
}

extern "C" void kernel_launch(void* const* d_in, const int* in_sizes, int n_in,
                              void* d_out, int out_size)
{
    const float* x = (const float*)d_in[0];
    const float* w = (const float*)d_in[1];
    if (n_in >= 2 && in_sizes[0] == 32 * 288 * 8 * 16 && in_sizes[1] == 4 * 256 * 14 * 14) {
        x = (const float*)d_in[1];
        w = (const float*)d_in[0];
    }
    const int smem_bytes = (288 * 32 * 4 + 2 * XHALF + 2 * NWARP * PWIDTH
                            + 2 * PWIDTH + 2 * 64) * (int)sizeof(float);
    cudaFuncSetAttribute(caps_route_kernel,
                         cudaFuncAttributeMaxDynamicSharedMemorySize, smem_bytes);
    dim3 grid(9, 32);   // (position chunk) x (out capsule)
    caps_route_kernel<<<grid, NTHR, smem_bytes>>>(x, w, (float*)d_out);
}

// round 14
// speedup vs baseline: 2.8798x; 1.1027x over previous
#include <cuda_runtime.h>
#include <math.h>

// CapsuleLayer dynamic routing, fully fused, weight-slab resident in SMEM.
//   x: (4,256,14,14) f32   weight: (32,288,8,16) f32   out: (4,512,12,12) f32
// Grid (9,32): CTA = (16 position-groups, output capsule o). 576 threads =
// two 288-thread halves; each half owns one 4-position group per outer iter.
// Weights staged once per CTA (coalesced LDG, swizzled conflict-free STS/LDS).
// x patch stored with padded stride 257 (conflict-free staging STS).
// ALL component math uses packed f32x2 (fma/mul/add.rn.f32x2 via PTX):
// priors = 256 FFMA2 instead of 512 FFMA; butterfly adds/muls halved.
// Routing: shift-free softmax; both pairs share one barrier set per iter.

#define GPOS 4
#define HALF_THR 288
#define NTHR 576
#define NWARP 9
#define GROUPS_PER_CHUNK 16
#define ITERS_PER_CTA 8
#define XSTRIDE 257
#define XHALF (18 * XSTRIDE)
#define PWIDTH 72              // per-warp partials: 2 pairs * 2 par * 18 (pad)

typedef unsigned long long u64;

#define FMA2(d, a, b) asm("fma.rn.f32x2 %0, %1, %2, %0;" : "+l"(d) : "l"(a), "l"(b))
#define MUL2(d, a, b) asm("mul.rn.f32x2 %0, %1, %2;" : "=l"(d) : "l"(a), "l"(b))
#define ADD2(d, a, b) asm("add.rn.f32x2 %0, %1, %2;" : "=l"(d) : "l"(a), "l"(b))

__device__ __forceinline__ u64 pack2(float lo, float hi) {
    u64 r; asm("mov.b64 %0, {%1, %2};" : "=l"(r) : "f"(lo), "f"(hi)); return r;
}
__device__ __forceinline__ float2 unpack2(u64 v) {
    float2 f; asm("mov.b64 {%0, %1}, %2;" : "=f"(f.x), "=f"(f.y) : "l"(v)); return f;
}

__global__ __launch_bounds__(NTHR, 1)
void caps_route_kernel(const float* __restrict__ x,
                       const float* __restrict__ w,
                       float* __restrict__ out)
{
    extern __shared__ float smem[];
    float4* s_w4   = (float4*)smem;                  // 288*32 float4 = 147456 B
    float*  s_x    = smem + 288 * 32 * 4;            // 2 halves * XHALF
    float*  s_part = s_x + 2 * XHALF;                // 2 halves * 9 * 72
    float*  s_red  = s_part + 2 * NWARP * PWIDTH;    // 2 halves * 72
    float*  s_out  = s_red + 2 * PWIDTH;             // 2 halves * 64

    const int tid  = threadIdx.x;
    const int h    = (tid >= HALF_THR) ? 1 : 0;
    const int htid = tid - h * HALF_THR;             // 0..287 == route k
    const int lane = tid & 31;
    const int wh   = htid >> 5;                      // warp-in-half == kk

    float* s_xh    = s_x    + h * XHALF;
    float* s_parth = s_part + h * NWARP * PWIDTH;
    float* s_redh  = s_red  + h * PWIDTH;
    float* s_outh  = s_out  + h * 64;

    const int o = blockIdx.y;

    // ---- stage full weight slab for o (147 KB), once per CTA
    {
        const float4* wbase = (const float4*)(w + (size_t)o * 288 * 128);
#pragma unroll
        for (int pass = 0; pass < 16; ++pass) {
            int idx = tid + pass * NTHR;             // warp reads one k, j=lane
            int k = idx >> 5;
            int j = idx & 31;
            s_w4[k * 32 + (j & ~7) + ((j & 7) ^ (k & 7))] = wbase[idx];
        }
    }

    // ---- strength-reduced x-staging constants (288 = 16*18)
    const int c0  = htid / 18;                       // 0..15
    const int rr  = htid - c0 * 18;                  // 0..17 == position
    const int khh = rr / 6;
    const int ww  = rr - khh * 6;
    const int kh  = wh / 3;
    const int kw  = wh - 3 * kh;
    const float* sxbase = s_xh + (kh * 6 + kw) * XSTRIDE + lane;  // lane == inc
    float* sxw = s_xh + rr * XSTRIDE + (c0 & 7) * 32 + (c0 >> 3);

    // lane -> (parity, component) after the merged butterfly:
    // comp = 8*bit1 + 4*bit2 + 2*bit3 + 1*bit4 (bit-set lane keeps upper block)
    const int par  = lane & 1;
    const int comp = ((lane & 2) ? 8 : 0) | ((lane & 4) ? 4 : 0)
                   | ((lane & 8) ? 2 : 0) | ((lane & 16) ? 1 : 0);
    const int sp_base = wh * PWIDTH + par * 18;      // + pair*36 (+comp / +16)

#pragma unroll 1
    for (int itg = 0; itg < ITERS_PER_CTA; ++itg) {
        const int nb  = blockIdx.x * GROUPS_PER_CHUNK + itg * 2 + h;
        const int b   = nb / 36;
        const int r   = nb - b * 36;
        const int oh  = r / 3;
        const int ow0 = (r - oh * 3) * GPOS;

        // ---- stage x patch (per half); conflict-free STS via padded stride
        {
            const float* xsrc = x + ((size_t)b * 256 + c0) * 196
                                  + (oh + khh) * 14 + ow0 + ww;
#pragma unroll
            for (int pass = 0; pass < 16; ++pass)
                sxw[pass * 2] = xsrc[pass * 3136];
        }
        __syncthreads();                             // x ready (+ weights, itg=0)

        // ---- priors (packed): pr2[g][c2] = packed (c=2*c2, 2*c2+1)
        u64 pr2[GPOS][8];
#pragma unroll
        for (int g = 0; g < GPOS; ++g)
#pragma unroll
            for (int c2 = 0; c2 < 8; ++c2) pr2[g][c2] = 0ull;

#pragma unroll
        for (int i = 0; i < 8; ++i) {
            u64 wv2[8];
#pragma unroll
            for (int jj = 0; jj < 4; ++jj) {
                int j = i * 4 + jj;
                float4 q = s_w4[htid * 32 + (j & ~7) + ((j & 7) ^ (htid & 7))];
                wv2[jj * 2 + 0] = pack2(q.x, q.y);
                wv2[jj * 2 + 1] = pack2(q.z, q.w);
            }
#pragma unroll
            for (int g = 0; g < GPOS; ++g) {
                float t  = sxbase[i * 32 + g * XSTRIDE];
                u64   t2 = pack2(t, t);
#pragma unroll
                for (int c2 = 0; c2 < 8; ++c2) FMA2(pr2[g][c2], t2, wv2[c2]);
            }
        }

        // ---- dynamic routing: 3 iterations; both pairs share one barrier set
        float logit[GPOS] = {0.0f, 0.0f, 0.0f, 0.0f};

#pragma unroll
        for (int it = 0; it < 3; ++it) {
#pragma unroll
            for (int p = 0; p < 2; ++p) {
                const int ga = 2 * p, gb = 2 * p + 1;
                u64 ym2[8];
                float zm = 0.0f;

                if (it == 0) {
                    // e == 1: parity split of raw priors, Z known (=288)
#pragma unroll
                    for (int c2 = 0; c2 < 8; ++c2) {
                        u64 a   = pr2[ga][c2];
                        u64 bq  = pr2[gb][c2];
                        u64 snd = par ? a : bq;
                        u64 rcv = __shfl_xor_sync(0xffffffffu, snd, 1);
                        u64 kp  = par ? bq : a;
                        ADD2(ym2[c2], kp, rcv);
                    }
                } else {
                    float ea = __expf(logit[ga]);
                    float eb = __expf(logit[gb]);
                    u64 ea2 = pack2(ea, ea), eb2 = pack2(eb, eb);
#pragma unroll
                    for (int c2 = 0; c2 < 8; ++c2) {
                        u64 a, bq;
                        MUL2(a,  ea2, pr2[ga][c2]);
                        MUL2(bq, eb2, pr2[gb][c2]);
                        u64 snd = par ? a : bq;
                        u64 rcv = __shfl_xor_sync(0xffffffffu, snd, 1);
                        u64 kp  = par ? bq : a;
                        ADD2(ym2[c2], kp, rcv);
                    }
                    {
                        float snd = par ? ea : eb;
                        float rcv = __shfl_xor_sync(0xffffffffu, snd, 1);
                        zm = (par ? eb : ea) + rcv;
                    }
                }
                // offset 2: comps 16 -> 8 (packed pairs 0-3 vs 4-7)
#pragma unroll
                for (int c2 = 0; c2 < 4; ++c2) {
                    u64 snd = (lane & 2) ? ym2[c2] : ym2[c2 + 4];
                    u64 rcv = __shfl_xor_sync(0xffffffffu, snd, 2);
                    u64 kp  = (lane & 2) ? ym2[c2 + 4] : ym2[c2];
                    ADD2(ym2[c2], kp, rcv);
                }
                // offset 4: 8 -> 4 (pairs 0-1 vs 2-3)
#pragma unroll
                for (int c2 = 0; c2 < 2; ++c2) {
                    u64 snd = (lane & 4) ? ym2[c2] : ym2[c2 + 2];
                    u64 rcv = __shfl_xor_sync(0xffffffffu, snd, 4);
                    u64 kp  = (lane & 4) ? ym2[c2 + 2] : ym2[c2];
                    ADD2(ym2[c2], kp, rcv);
                }
                // offset 8: 4 -> 2 (pair 0 vs 1)
                {
                    u64 snd = (lane & 8) ? ym2[0] : ym2[1];
                    u64 rcv = __shfl_xor_sync(0xffffffffu, snd, 8);
                    u64 kp  = (lane & 8) ? ym2[1] : ym2[0];
                    ADD2(ym2[0], kp, rcv);
                }
                // offset 16: 2 -> 1 (within pair 0: unpack)
                float y0;
                {
                    float2 f = unpack2(ym2[0]);
                    float snd = (lane & 16) ? f.x : f.y;
                    float rcv = __shfl_xor_sync(0xffffffffu, snd, 16);
                    y0 = ((lane & 16) ? f.y : f.x) + rcv;
                }
                if (it != 0) {
                    zm += __shfl_xor_sync(0xffffffffu, zm, 2);
                    zm += __shfl_xor_sync(0xffffffffu, zm, 4);
                    zm += __shfl_xor_sync(0xffffffffu, zm, 8);
                    zm += __shfl_xor_sync(0xffffffffu, zm, 16);
                }

                s_parth[sp_base + p * 36 + comp] = y0;
                if (it != 0 && lane < 2) s_parth[sp_base + p * 36 + 16] = zm;
            }
            __syncthreads();
            if (htid < PWIDTH) {
                float a = 0.0f;
#pragma unroll
                for (int wq = 0; wq < NWARP; ++wq)
                    a += s_parth[wq * PWIDTH + htid];
                s_redh[htid] = a;
            }
            __syncthreads();

            // epilogue for all 4 positions (packed FMAs + broadcast LDS.64)
#pragma unroll
            for (int p = 0; p < 2; ++p) {
                const int ga = 2 * p, gb = 2 * p + 1;
                const float* rp = s_redh + p * 36;   // 8B-aligned (36*4=144B)
                float Za = (it == 0) ? 288.0f : rp[16];
                float Zb = (it == 0) ? 288.0f : rp[18 + 16];
                float iZa = __fdividef(1.0f, Za);
                float iZb = __fdividef(1.0f, Zb);
                u64 sqa2 = 0ull, da2 = 0ull, sqb2 = 0ull, db2 = 0ull;
#pragma unroll
                for (int c2 = 0; c2 < 8; ++c2) {
                    u64 va2 = *(const u64*)(rp + 2 * c2);        // aligned
                    u64 vb2 = *(const u64*)(rp + 18 + 2 * c2);   // +72B aligned
                    FMA2(sqa2, va2, va2);  FMA2(da2, pr2[ga][c2], va2);
                    FMA2(sqb2, vb2, vb2);  FMA2(db2, pr2[gb][c2], vb2);
                }
                float2 fa = unpack2(sqa2), fb = unpack2(sqb2);
                float2 ga2 = unpack2(da2), gb2 = unpack2(db2);
                float sqa = fa.x + fa.y, sqb = fb.x + fb.y;
                float da  = ga2.x + ga2.y, db = gb2.x + gb2.y;
                sqa *= iZa * iZa;  sqb *= iZb * iZb;
                float sca = __fdividef(sqrtf(sqa), 1.0f + sqa);
                float scb = __fdividef(sqrtf(sqb), 1.0f + sqb);
                if (it < 2) {
                    logit[ga] += sca * (da * iZa);
                    logit[gb] += scb * (db * iZb);
                } else {
                    float ova = sca * iZa, ovb = scb * iZb;
                    if (htid < 16) {
                        s_outh[htid * GPOS + ga] = rp[htid]      * ova;
                        s_outh[htid * GPOS + gb] = rp[18 + htid] * ovb;
                    }
                }
            }
        }

        __syncthreads();                             // s_out ready
        // ---- output: 64 threads/half, 16 rows x 4 contiguous floats
        if (htid < 16 * GPOS) {
            int c = htid >> 2;
            int g = htid & 3;
            out[(((size_t)b * 512 + o * 16 + c) * 12 + oh) * 12 + (ow0 + g)]
                = s_outh[c * GPOS + g];
        }
    }
}

extern "C" void kernel_launch(void* const* d_in, const int* in_sizes, int n_in,
                              void* d_out, int out_size)
{
    const float* x = (const float*)d_in[0];
    const float* w = (const float*)d_in[1];
    if (n_in >= 2 && in_sizes[0] == 32 * 288 * 8 * 16 && in_sizes[1] == 4 * 256 * 14 * 14) {
        x = (const float*)d_in[1];
        w = (const float*)d_in[0];
    }
    const int smem_bytes = (288 * 32 * 4 + 2 * XHALF + 2 * NWARP * PWIDTH
                            + 2 * PWIDTH + 2 * 64) * (int)sizeof(float);
    cudaFuncSetAttribute(caps_route_kernel,
                         cudaFuncAttributeMaxDynamicSharedMemorySize, smem_bytes);
    dim3 grid(9, 32);   // (position chunk) x (out capsule)
    caps_route_kernel<<<grid, NTHR, smem_bytes>>>(x, w, (float*)d_out);
}